// round 12
// baseline (speedup 1.0000x reference)
#include <cuda_runtime.h>
#include <cuda_bf16.h>
#include <math.h>
#include <stdint.h>

#define NTOK 16384
#define CDIM 8192
#define HDIM 2048
#define IDIM 8192

// ---------------------------------------------------------------------------
// Scratch (__device__ globals; allocation-free rule)
// ---------------------------------------------------------------------------
__device__ __align__(256) __nv_bfloat16 g_Wgh[(size_t)IDIM * HDIM];
__device__ __align__(256) __nv_bfloat16 g_Wgl[(size_t)IDIM * HDIM];
__device__ __align__(256) __nv_bfloat16 g_Wuh[(size_t)IDIM * HDIM];
__device__ __align__(256) __nv_bfloat16 g_Wul[(size_t)IDIM * HDIM];
__device__ __align__(256) __nv_bfloat16 g_Wdh[(size_t)HDIM * IDIM];
__device__ __align__(256) __nv_bfloat16 g_Wdl[(size_t)HDIM * IDIM];
__device__ __align__(256) __nv_bfloat16 g_hh[(size_t)CDIM * IDIM];  // silu(g)*u hi
__device__ __align__(256) __nv_bfloat16 g_hl[(size_t)CDIM * IDIM];  // silu(g)*u lo
__device__ __align__(256) float g_down[(size_t)CDIM * HDIM];

// ---------------------------------------------------------------------------
// helpers (plain sm_80-era PTX only)
// ---------------------------------------------------------------------------
__device__ __forceinline__ uint32_t smem_u32(const void* p) {
    return (uint32_t)__cvta_generic_to_shared(p);
}
__device__ __forceinline__ void ldsm4(uint32_t a, uint32_t& r0, uint32_t& r1,
                                      uint32_t& r2, uint32_t& r3) {
    asm volatile("ldmatrix.sync.aligned.m8n8.x4.shared.b16 {%0,%1,%2,%3}, [%4];"
                 : "=r"(r0), "=r"(r1), "=r"(r2), "=r"(r3) : "r"(a));
}
__device__ __forceinline__ void hmma(float* c, const uint32_t* a,
                                     uint32_t b0, uint32_t b1) {
    asm volatile(
        "mma.sync.aligned.m16n8k16.row.col.f32.bf16.bf16.f32 "
        "{%0,%1,%2,%3},{%4,%5,%6,%7},{%8,%9},{%0,%1,%2,%3};"
        : "+f"(c[0]), "+f"(c[1]), "+f"(c[2]), "+f"(c[3])
        : "r"(a[0]), "r"(a[1]), "r"(a[2]), "r"(a[3]), "r"(b0), "r"(b1));
}
// fp32 -> (hi, lo) bf16 split of 4 consecutive K elements; 8B packed stores
__device__ __forceinline__ void split_store(char* hi, char* lo, float4 v) {
    __nv_bfloat162 h0 = __floats2bfloat162_rn(v.x, v.y);
    __nv_bfloat162 h1 = __floats2bfloat162_rn(v.z, v.w);
    float2 f0 = __bfloat1622float2(h0);
    float2 f1 = __bfloat1622float2(h1);
    __nv_bfloat162 l0 = __floats2bfloat162_rn(v.x - f0.x, v.y - f0.y);
    __nv_bfloat162 l1 = __floats2bfloat162_rn(v.z - f1.x, v.w - f1.y);
    uint32_t h0u = *reinterpret_cast<uint32_t*>(&h0);
    uint32_t h1u = *reinterpret_cast<uint32_t*>(&h1);
    uint32_t l0u = *reinterpret_cast<uint32_t*>(&l0);
    uint32_t l1u = *reinterpret_cast<uint32_t*>(&l1);
    *reinterpret_cast<uint2*>(hi) = make_uint2(h0u, h1u);
    *reinterpret_cast<uint2*>(lo) = make_uint2(l0u, l1u);
}
__device__ __forceinline__ void split4(float4 v, uint2& hi, uint2& lo) {
    __nv_bfloat162 h0 = __floats2bfloat162_rn(v.x, v.y);
    __nv_bfloat162 h1 = __floats2bfloat162_rn(v.z, v.w);
    float2 f0 = __bfloat1622float2(h0);
    float2 f1 = __bfloat1622float2(h1);
    __nv_bfloat162 l0 = __floats2bfloat162_rn(v.x - f0.x, v.y - f0.y);
    __nv_bfloat162 l1 = __floats2bfloat162_rn(v.z - f1.x, v.w - f1.y);
    hi = make_uint2(*reinterpret_cast<uint32_t*>(&h0), *reinterpret_cast<uint32_t*>(&h1));
    lo = make_uint2(*reinterpret_cast<uint32_t*>(&l0), *reinterpret_cast<uint32_t*>(&l1));
}
// two fp32 -> bf16x2 hi + bf16x2 lo words
__device__ __forceinline__ void split2_words(float v0, float v1,
                                             uint32_t& hi, uint32_t& lo) {
    __nv_bfloat162 h = __floats2bfloat162_rn(v0, v1);
    float2 hf = __bfloat1622float2(h);
    __nv_bfloat162 l = __floats2bfloat162_rn(v0 - hf.x, v1 - hf.y);
    hi = *reinterpret_cast<uint32_t*>(&h);
    lo = *reinterpret_cast<uint32_t*>(&l);
}
__device__ __forceinline__ float silu(float g) { return g / (1.f + __expf(-g)); }

// smem rows: 32 bf16 padded to 40 (80B = 5x16B) — conflict-free ldmatrix
#define ROWB 80
// k1 planes: A_hi(128r) A_lo | G_hi(64r) G_lo | U_hi U_lo
#define K1_ALO   10240
#define K1_GHI   20480
#define K1_GLO   25600
#define K1_UHI   30720
#define K1_ULO   35840
#define STAGE1   40960
#define SMEM1    (2 * STAGE1)   // 80 KB -> 2 CTAs/SM
// k2 planes: A_hi(128r) A_lo | B_hi(128r) B_lo
#define K2_ALO   10240
#define K2_BHI   20480
#define K2_BLO   30720
#define STAGE2   40960
#define SMEM2    (2 * STAGE2)   // 80 KB -> 2 CTAs/SM

#define NC1 (HDIM / 32)   // 64 chunks
#define NC2 (IDIM / 32)   // 256 chunks

// ---------------------------------------------------------------------------
// pre-pass: fp32 weight -> bf16 hi/lo planes
// ---------------------------------------------------------------------------
__global__ __launch_bounds__(256)
void conv_w(const float4* __restrict__ W, __nv_bfloat16* __restrict__ hi,
            __nv_bfloat16* __restrict__ lo, int n4)
{
    for (int i = blockIdx.x * 256 + threadIdx.x; i < n4; i += gridDim.x * 256) {
        uint2 h, l;
        split4(W[i], h, l);
        *reinterpret_cast<uint2*>(hi + 4 * (size_t)i) = h;
        *reinterpret_cast<uint2*>(lo + 4 * (size_t)i) = l;
    }
}

// ---------------------------------------------------------------------------
// Kernel 1: gather + dual GEMM (gate,up) + SiLU. CTA 128m x 64n, 2 CTAs/SM.
// R11 structure; B staged from pre-split planes (pure LDG/STS, no cvt).
// ---------------------------------------------------------------------------
__global__ __launch_bounds__(256, 2)
void k1_gateup(const float* __restrict__ x, const int* __restrict__ fg)
{
    extern __shared__ __align__(128) char sm[];
    const uint32_t smb = smem_u32(sm);
    const int tid  = threadIdx.x;
    const int wid  = tid >> 5;
    const int lane = tid & 31;
    const int m0 = blockIdx.x * 128;   // m fastest -> B tiles L2-resident
    const int n0 = blockIdx.y * 64;

    // A staging (fp32 + split): 8 threads/row, one float4 each, 4 rows/thread
    const int rbase = tid >> 3;
    const int c4    = (tid & 7) * 4;
    const float* pA[4];
    int stsA[4];
#pragma unroll
    for (int j = 0; j < 4; j++) {
        int row = rbase + 32 * j;
        pA[j] = x + (size_t)__ldg(fg + m0 + row) * HDIM + c4;
        stsA[j] = row * ROWB + (tid & 7) * 8;
    }
    // B staging from pre-split planes: 64 rows, 4 thr/row, 16B (8 bf16) each
    const int brow = tid >> 2;
    const size_t bOff = (size_t)(n0 + brow) * HDIM + (tid & 3) * 8;
    const int stsB = brow * ROWB + (tid & 3) * 16;

    // ldmatrix lane geometry
    const int laneRow = ((lane >> 3) & 1) * 8 + (lane & 7);
    const int laneK   = (lane >> 4) * 16;
    const int R       = 32 * (wid & 3);
    const int bSec    = (wid >= 4) ? K1_UHI : K1_GHI;   // lo plane = +5120

    float acc[2][8][4];
#pragma unroll
    for (int f = 0; f < 2; f++)
#pragma unroll
        for (int n = 0; n < 8; n++)
#pragma unroll
            for (int q = 0; q < 4; q++) acc[f][n][q] = 0.f;

#define K1_STAGE(DST, K0) do {                                                 \
    char* st = (DST);                                                          \
    float4 a0 = *reinterpret_cast<const float4*>(pA[0] + (K0));                \
    float4 a1 = *reinterpret_cast<const float4*>(pA[1] + (K0));                \
    float4 a2 = *reinterpret_cast<const float4*>(pA[2] + (K0));                \
    float4 a3 = *reinterpret_cast<const float4*>(pA[3] + (K0));                \
    uint4 vGh = *reinterpret_cast<const uint4*>(g_Wgh + bOff + (K0));          \
    uint4 vGl = *reinterpret_cast<const uint4*>(g_Wgl + bOff + (K0));          \
    uint4 vUh = *reinterpret_cast<const uint4*>(g_Wuh + bOff + (K0));          \
    uint4 vUl = *reinterpret_cast<const uint4*>(g_Wul + bOff + (K0));          \
    split_store(st + stsA[0], st + K1_ALO + stsA[0], a0);                      \
    split_store(st + stsA[1], st + K1_ALO + stsA[1], a1);                      \
    split_store(st + stsA[2], st + K1_ALO + stsA[2], a2);                      \
    split_store(st + stsA[3], st + K1_ALO + stsA[3], a3);                      \
    *reinterpret_cast<uint4*>(st + K1_GHI + stsB) = vGh;                       \
    *reinterpret_cast<uint4*>(st + K1_GLO + stsB) = vGl;                       \
    *reinterpret_cast<uint4*>(st + K1_UHI + stsB) = vUh;                       \
    *reinterpret_cast<uint4*>(st + K1_ULO + stsB) = vUl;                       \
} while (0)

    K1_STAGE(sm, 0);

#pragma unroll 1
    for (int c = 0; c < NC1; c++) {
        __syncthreads();
        const uint32_t sb = smb + (uint32_t)(c & 1) * STAGE1;
#pragma unroll
        for (int s = 0; s < 2; s++) {
            const uint32_t ab = sb + (uint32_t)((R + laneRow) * ROWB + laneK + 32 * s);
            uint32_t ah[2][4], al[2][4];
            ldsm4(ab,                      ah[0][0], ah[0][1], ah[0][2], ah[0][3]);
            ldsm4(ab + 16 * ROWB,          ah[1][0], ah[1][1], ah[1][2], ah[1][3]);
            ldsm4(ab + K1_ALO,             al[0][0], al[0][1], al[0][2], al[0][3]);
            ldsm4(ab + K1_ALO + 16 * ROWB, al[1][0], al[1][1], al[1][2], al[1][3]);
#pragma unroll
            for (int gp = 0; gp < 4; gp++) {
                const uint32_t bb = sb + (uint32_t)(bSec +
                    (16 * gp + laneRow) * ROWB + laneK + 32 * s);
                uint32_t bh[4], bl[4];
                ldsm4(bb,        bh[0], bh[1], bh[2], bh[3]);
                ldsm4(bb + 5120, bl[0], bl[1], bl[2], bl[3]);
#pragma unroll
                for (int f = 0; f < 2; f++)
#pragma unroll
                    for (int h = 0; h < 2; h++) {
                        float* cc = acc[f][2 * gp + h];
                        hmma(cc, ah[f], bh[h], bh[2 + h]);
                        hmma(cc, ah[f], bl[h], bl[2 + h]);
                        hmma(cc, al[f], bh[h], bh[2 + h]);
                    }
            }
        }
        if (c + 1 < NC1)
            K1_STAGE(sm + (size_t)((c + 1) & 1) * STAGE1, (c + 1) * 32);
    }
#undef K1_STAGE

    // ---- epilogue: up warps park 32x64 tiles in smem; gate warps combine ----
    __syncthreads();
    float* upbuf = reinterpret_cast<float*>(sm);   // 4 x (32 x 68) floats
    if (wid >= 4) {
        float* base = upbuf + (wid - 4) * 2176;
#pragma unroll
        for (int f = 0; f < 2; f++)
#pragma unroll
            for (int n = 0; n < 8; n++) {
                int row = 16 * f + (lane >> 2);
                int col = 8 * n + (lane & 3) * 2;
                float* b0 = base + row * 68 + col;
                b0[0] = acc[f][n][0]; b0[1] = acc[f][n][1];
                float* b1 = b0 + 8 * 68;
                b1[0] = acc[f][n][2]; b1[1] = acc[f][n][3];
            }
    }
    __syncthreads();
    if (wid < 4) {
        const float* base = upbuf + wid * 2176;
#pragma unroll
        for (int f = 0; f < 2; f++)
#pragma unroll
            for (int n = 0; n < 8; n++) {
                int row = 16 * f + (lane >> 2);
                int col = 8 * n + (lane & 3) * 2;
                const float* b0 = base + row * 68 + col;
                const float* b1 = b0 + 8 * 68;
                size_t o0 = (size_t)(m0 + R + row) * IDIM + n0 + col;
                size_t o1 = o0 + (size_t)8 * IDIM;
                uint32_t hi, lo;
                split2_words(silu(acc[f][n][0]) * b0[0],
                             silu(acc[f][n][1]) * b0[1], hi, lo);
                *reinterpret_cast<uint32_t*>(g_hh + o0) = hi;
                *reinterpret_cast<uint32_t*>(g_hl + o0) = lo;
                split2_words(silu(acc[f][n][2]) * b1[0],
                             silu(acc[f][n][3]) * b1[1], hi, lo);
                *reinterpret_cast<uint32_t*>(g_hh + o1) = hi;
                *reinterpret_cast<uint32_t*>(g_hl + o1) = lo;
            }
    }
}

// ---------------------------------------------------------------------------
// Kernel 2: down projection. CTA 128m x 128n, 8 warps 4m x 2n, 2 CTAs/SM.
// Fully conversion-free: A (g_hh/g_hl) and B (Wd planes) pure LDG/STS.
// ---------------------------------------------------------------------------
__global__ __launch_bounds__(256, 2)
void k2_down()
{
    extern __shared__ __align__(128) char sm[];
    const uint32_t smb = smem_u32(sm);
    const int tid  = threadIdx.x;
    const int wid  = tid >> 5;
    const int lane = tid & 31;
    const int m0 = blockIdx.x * 128;
    const int n0 = blockIdx.y * 128;

    // staging: 128 rows/plane, 2 thr/row, 2x16B per plane per thread
    const int prow = tid >> 1;
    const int ph   = tid & 1;                   // half of the 64B row
    const size_t aOff = (size_t)(m0 + prow) * IDIM + ph * 16;
    const size_t bOff = (size_t)(n0 + prow) * IDIM + ph * 16;
    const int sts = prow * ROWB + ph * 32;

    const int laneRow = ((lane >> 3) & 1) * 8 + (lane & 7);
    const int laneK   = (lane >> 4) * 16;
    const int R       = 32 * (wid & 3);
    const int Cw      = 64 * (wid >> 2);

    float acc[2][8][4];
#pragma unroll
    for (int f = 0; f < 2; f++)
#pragma unroll
        for (int n = 0; n < 8; n++)
#pragma unroll
            for (int q = 0; q < 4; q++) acc[f][n][q] = 0.f;

#define K2_STAGE(DST, K0) do {                                                 \
    char* st = (DST);                                                          \
    uint4 ah0 = *reinterpret_cast<const uint4*>(g_hh  + aOff + (K0));          \
    uint4 ah1 = *reinterpret_cast<const uint4*>(g_hh  + aOff + (K0) + 8);      \
    uint4 al0 = *reinterpret_cast<const uint4*>(g_hl  + aOff + (K0));          \
    uint4 al1 = *reinterpret_cast<const uint4*>(g_hl  + aOff + (K0) + 8);      \
    uint4 bh0 = *reinterpret_cast<const uint4*>(g_Wdh + bOff + (K0));          \
    uint4 bh1 = *reinterpret_cast<const uint4*>(g_Wdh + bOff + (K0) + 8);      \
    uint4 bl0 = *reinterpret_cast<const uint4*>(g_Wdl + bOff + (K0));          \
    uint4 bl1 = *reinterpret_cast<const uint4*>(g_Wdl + bOff + (K0) + 8);      \
    *reinterpret_cast<uint4*>(st + sts)                = ah0;                  \
    *reinterpret_cast<uint4*>(st + sts + 16)           = ah1;                  \
    *reinterpret_cast<uint4*>(st + K2_ALO + sts)       = al0;                  \
    *reinterpret_cast<uint4*>(st + K2_ALO + sts + 16)  = al1;                  \
    *reinterpret_cast<uint4*>(st + K2_BHI + sts)       = bh0;                  \
    *reinterpret_cast<uint4*>(st + K2_BHI + sts + 16)  = bh1;                  \
    *reinterpret_cast<uint4*>(st + K2_BLO + sts)       = bl0;                  \
    *reinterpret_cast<uint4*>(st + K2_BLO + sts + 16)  = bl1;                  \
} while (0)

    K2_STAGE(sm, 0);

#pragma unroll 1
    for (int c = 0; c < NC2; c++) {
        __syncthreads();
        const uint32_t sb = smb + (uint32_t)(c & 1) * STAGE2;
#pragma unroll
        for (int s = 0; s < 2; s++) {
            const uint32_t ab = sb + (uint32_t)((R + laneRow) * ROWB + laneK + 32 * s);
            uint32_t ah[2][4], al[2][4];
            ldsm4(ab,                      ah[0][0], ah[0][1], ah[0][2], ah[0][3]);
            ldsm4(ab + 16 * ROWB,          ah[1][0], ah[1][1], ah[1][2], ah[1][3]);
            ldsm4(ab + K2_ALO,             al[0][0], al[0][1], al[0][2], al[0][3]);
            ldsm4(ab + K2_ALO + 16 * ROWB, al[1][0], al[1][1], al[1][2], al[1][3]);
#pragma unroll
            for (int gp = 0; gp < 4; gp++) {
                const uint32_t bb = sb + (uint32_t)(K2_BHI +
                    (Cw + 16 * gp + laneRow) * ROWB + laneK + 32 * s);
                uint32_t bh[4], bl[4];
                ldsm4(bb,         bh[0], bh[1], bh[2], bh[3]);
                ldsm4(bb + 10240, bl[0], bl[1], bl[2], bl[3]);
#pragma unroll
                for (int f = 0; f < 2; f++)
#pragma unroll
                    for (int h = 0; h < 2; h++) {
                        float* cc = acc[f][2 * gp + h];
                        hmma(cc, ah[f], bh[h], bh[2 + h]);
                        hmma(cc, ah[f], bl[h], bl[2 + h]);
                        hmma(cc, al[f], bh[h], bh[2 + h]);
                    }
            }
        }
        if (c + 1 < NC2)
            K2_STAGE(sm + (size_t)((c + 1) & 1) * STAGE2, (c + 1) * 32);
    }
#undef K2_STAGE

    // epilogue: direct fp32 stores
#pragma unroll
    for (int f = 0; f < 2; f++)
#pragma unroll
        for (int n = 0; n < 8; n++) {
            int row = m0 + R + 16 * f + (lane >> 2);
            int col = n0 + Cw + 8 * n + (lane & 3) * 2;
            float* o0 = g_down + (size_t)row * HDIM + col;
            float* o1 = o0 + (size_t)8 * HDIM;
            *reinterpret_cast<float2*>(o0) = make_float2(acc[f][n][0], acc[f][n][1]);
            *reinterpret_cast<float2*>(o1) = make_float2(acc[f][n][2], acc[f][n][3]);
        }
}

// ---------------------------------------------------------------------------
// Kernel 3: scatter
// ---------------------------------------------------------------------------
__global__ __launch_bounds__(256)
void scatter_kernel(const int* __restrict__ scatter_indices,
                    float* __restrict__ out)
{
    const int t = blockIdx.x;
    const int c = scatter_indices[t];
    const float4* src = reinterpret_cast<const float4*>(g_down + (size_t)c * HDIM);
    float4*       dst = reinterpret_cast<float4*>(out + (size_t)t * HDIM);
#pragma unroll
    for (int j = threadIdx.x; j < HDIM / 4; j += 256)
        dst[j] = src[j];
}

// ---------------------------------------------------------------------------
extern "C" void kernel_launch(void* const* d_in, const int* in_sizes, int n_in,
                              void* d_out, int out_size)
{
    const float* x  = (const float*)d_in[0];
    const float* Wg = (const float*)d_in[1];
    const float* Wu = (const float*)d_in[2];
    const float* Wd = (const float*)d_in[3];
    const int*   fg = (const int*)d_in[4];
    const int*   sc = (const int*)d_in[5];
    float*       out = (float*)d_out;

    cudaFuncSetAttribute(k1_gateup, cudaFuncAttributeMaxDynamicSharedMemorySize, SMEM1);
    cudaFuncSetAttribute(k2_down,   cudaFuncAttributeMaxDynamicSharedMemorySize, SMEM2);

    __nv_bfloat16 *wgh, *wgl, *wuh, *wul, *wdh, *wdl;
    cudaGetSymbolAddress((void**)&wgh, g_Wgh);
    cudaGetSymbolAddress((void**)&wgl, g_Wgl);
    cudaGetSymbolAddress((void**)&wuh, g_Wuh);
    cudaGetSymbolAddress((void**)&wul, g_Wul);
    cudaGetSymbolAddress((void**)&wdh, g_Wdh);
    cudaGetSymbolAddress((void**)&wdl, g_Wdl);

    const int n4 = (IDIM * HDIM) / 4;
    conv_w<<<4096, 256>>>((const float4*)Wg, wgh, wgl, n4);
    conv_w<<<4096, 256>>>((const float4*)Wu, wuh, wul, n4);
    conv_w<<<4096, 256>>>((const float4*)Wd, wdh, wdl, n4);

    dim3 g1(CDIM / 128, IDIM / 64);    // (64 m fastest, 128 n)
    k1_gateup<<<g1, 256, SMEM1>>>(x, fg);

    dim3 g2(CDIM / 128, HDIM / 128);   // (64 m fastest, 16 n)
    k2_down<<<g2, 256, SMEM2>>>();

    scatter_kernel<<<NTOK, 256>>>(sc, out);
}

// round 13
// speedup vs baseline: 1.4649x; 1.4649x over previous
#include <cuda_runtime.h>
#include <cuda_fp16.h>
#include <math.h>
#include <stdint.h>

#define NTOK 16384
#define CDIM 8192
#define HDIM 2048
#define IDIM 8192

// Scratch (allocation-free rule: __device__ globals)
__device__ __align__(256) float g_h[(size_t)CDIM * IDIM];      // silu(g)*u
__device__ __align__(256) float g_down[(size_t)CDIM * HDIM];

// ---------------------------------------------------------------------------
// helpers (plain sm_80-era PTX only)
// ---------------------------------------------------------------------------
__device__ __forceinline__ uint32_t smem_u32(const void* p) {
    return (uint32_t)__cvta_generic_to_shared(p);
}
__device__ __forceinline__ void ldsm4(uint32_t a, uint32_t& r0, uint32_t& r1,
                                      uint32_t& r2, uint32_t& r3) {
    asm volatile("ldmatrix.sync.aligned.m8n8.x4.shared.b16 {%0,%1,%2,%3}, [%4];"
                 : "=r"(r0), "=r"(r1), "=r"(r2), "=r"(r3) : "r"(a));
}
// fp16 x fp16 -> fp32 accum MMA
__device__ __forceinline__ void hmma(float* c, const uint32_t* a,
                                     uint32_t b0, uint32_t b1) {
    asm volatile(
        "mma.sync.aligned.m16n8k16.row.col.f32.f16.f16.f32 "
        "{%0,%1,%2,%3},{%4,%5,%6,%7},{%8,%9},{%0,%1,%2,%3};"
        : "+f"(c[0]), "+f"(c[1]), "+f"(c[2]), "+f"(c[3])
        : "r"(a[0]), "r"(a[1]), "r"(a[2]), "r"(a[3]), "r"(b0), "r"(b1));
}
// fp32x4 -> fp16 hi (8B) + fp16 lo (8B); A-operand split-2
__device__ __forceinline__ void split_store_h(char* hi, char* lo, float4 v) {
    __half2 h0 = __floats2half2_rn(v.x, v.y);
    __half2 h1 = __floats2half2_rn(v.z, v.w);
    float2 f0 = __half22float2(h0);
    float2 f1 = __half22float2(h1);
    __half2 l0 = __floats2half2_rn(v.x - f0.x, v.y - f0.y);
    __half2 l1 = __floats2half2_rn(v.z - f1.x, v.w - f1.y);
    uint32_t h0u = *reinterpret_cast<uint32_t*>(&h0);
    uint32_t h1u = *reinterpret_cast<uint32_t*>(&h1);
    uint32_t l0u = *reinterpret_cast<uint32_t*>(&l0);
    uint32_t l1u = *reinterpret_cast<uint32_t*>(&l1);
    *reinterpret_cast<uint2*>(hi) = make_uint2(h0u, h1u);
    *reinterpret_cast<uint2*>(lo) = make_uint2(l0u, l1u);
}
// fp32x8 -> fp16x8 (16B), B-operand single precision
__device__ __forceinline__ uint4 cvt8h(float4 v0, float4 v1) {
    __half2 a = __floats2half2_rn(v0.x, v0.y);
    __half2 b = __floats2half2_rn(v0.z, v0.w);
    __half2 c = __floats2half2_rn(v1.x, v1.y);
    __half2 d = __floats2half2_rn(v1.z, v1.w);
    return make_uint4(*reinterpret_cast<uint32_t*>(&a),
                      *reinterpret_cast<uint32_t*>(&b),
                      *reinterpret_cast<uint32_t*>(&c),
                      *reinterpret_cast<uint32_t*>(&d));
}
// fp32x4 -> fp16x4 (8B)
__device__ __forceinline__ uint2 cvt4h(float4 v) {
    __half2 a = __floats2half2_rn(v.x, v.y);
    __half2 b = __floats2half2_rn(v.z, v.w);
    return make_uint2(*reinterpret_cast<uint32_t*>(&a),
                      *reinterpret_cast<uint32_t*>(&b));
}
__device__ __forceinline__ float silu(float g) { return g / (1.f + __expf(-g)); }

// smem rows: 32 fp16 padded to 40 (80B = 5x16B) — conflict-free ldmatrix
#define ROWB 80
// k1 planes: A_hi(128r) A_lo | G(64r) | U(64r)
#define K1_ALO   10240
#define K1_G     20480
#define K1_U     25600
#define STAGE1   30720
#define SMEM1    (2 * STAGE1)   // 60 KB -> 2 CTAs/SM
// k2 planes: A_hi(128r) A_lo | B(128r)
#define K2_ALO   10240
#define K2_B     20480
#define STAGE2   30720
#define SMEM2    (2 * STAGE2)   // 60 KB -> 2 CTAs/SM

#define NC1 (HDIM / 32)   // 64 chunks
#define NC2 (IDIM / 32)   // 256 chunks

// ---------------------------------------------------------------------------
// Kernel 1: gather + dual GEMM (gate,up) + SiLU. CTA 128m x 64n, 2 CTAs/SM.
// Warps 0-3 gate (32m x 64n each), warps 4-7 up. fp16 2-term MMA.
// ---------------------------------------------------------------------------
__global__ __launch_bounds__(256, 2)
void k1_gateup(const float* __restrict__ x,
               const float* __restrict__ Wg,
               const float* __restrict__ Wu,
               const int* __restrict__ fg)
{
    extern __shared__ __align__(128) char sm[];
    const uint32_t smb = smem_u32(sm);
    const int tid  = threadIdx.x;
    const int wid  = tid >> 5;
    const int lane = tid & 31;
    const int m0 = blockIdx.x * 128;   // m fastest -> B tiles L2-resident
    const int n0 = blockIdx.y * 64;

    // A staging: 8 threads/row, one float4 each, 4 rows/thread (split-2 fp16)
    const int rbase = tid >> 3;
    const int c4    = (tid & 7) * 4;
    const float* pA[4];
    int stsA[4];
#pragma unroll
    for (int j = 0; j < 4; j++) {
        int row = rbase + 32 * j;
        pA[j] = x + (size_t)__ldg(fg + m0 + row) * HDIM + c4;
        stsA[j] = row * ROWB + (tid & 7) * 8;
    }
    // B staging: 64 rows, 4 threads/row, 8 floats -> 8 fp16 (16B) per matrix
    const int brow = tid >> 2;
    const float* pG = Wg + (size_t)(n0 + brow) * HDIM + (tid & 3) * 8;
    const float* pU = Wu + (size_t)(n0 + brow) * HDIM + (tid & 3) * 8;
    const int stsB = brow * ROWB + (tid & 3) * 16;

    // ldmatrix lane geometry
    const int laneRow = ((lane >> 3) & 1) * 8 + (lane & 7);
    const int laneK   = (lane >> 4) * 16;
    const int R       = 32 * (wid & 3);
    const int bSec    = (wid >= 4) ? K1_U : K1_G;

    float acc[2][8][4];
#pragma unroll
    for (int f = 0; f < 2; f++)
#pragma unroll
        for (int n = 0; n < 8; n++)
#pragma unroll
            for (int q = 0; q < 4; q++) acc[f][n][q] = 0.f;

#define K1_STAGE(DST, K0) do {                                                 \
    char* st = (DST);                                                          \
    float4 a0 = *reinterpret_cast<const float4*>(pA[0] + (K0));                \
    float4 a1 = *reinterpret_cast<const float4*>(pA[1] + (K0));                \
    float4 a2 = *reinterpret_cast<const float4*>(pA[2] + (K0));                \
    float4 a3 = *reinterpret_cast<const float4*>(pA[3] + (K0));                \
    float4 gg0 = *reinterpret_cast<const float4*>(pG + (K0));                  \
    float4 gg1 = *reinterpret_cast<const float4*>(pG + (K0) + 4);              \
    float4 uu0 = *reinterpret_cast<const float4*>(pU + (K0));                  \
    float4 uu1 = *reinterpret_cast<const float4*>(pU + (K0) + 4);              \
    split_store_h(st + stsA[0], st + K1_ALO + stsA[0], a0);                    \
    split_store_h(st + stsA[1], st + K1_ALO + stsA[1], a1);                    \
    split_store_h(st + stsA[2], st + K1_ALO + stsA[2], a2);                    \
    split_store_h(st + stsA[3], st + K1_ALO + stsA[3], a3);                    \
    *reinterpret_cast<uint4*>(st + K1_G + stsB) = cvt8h(gg0, gg1);             \
    *reinterpret_cast<uint4*>(st + K1_U + stsB) = cvt8h(uu0, uu1);             \
} while (0)

    K1_STAGE(sm, 0);

#pragma unroll 1
    for (int c = 0; c < NC1; c++) {
        __syncthreads();
        const uint32_t sb = smb + (uint32_t)(c & 1) * STAGE1;
#pragma unroll
        for (int s = 0; s < 2; s++) {
            const uint32_t ab = sb + (uint32_t)((R + laneRow) * ROWB + laneK + 32 * s);
            uint32_t ah[2][4], al[2][4];
            ldsm4(ab,                      ah[0][0], ah[0][1], ah[0][2], ah[0][3]);
            ldsm4(ab + 16 * ROWB,          ah[1][0], ah[1][1], ah[1][2], ah[1][3]);
            ldsm4(ab + K1_ALO,             al[0][0], al[0][1], al[0][2], al[0][3]);
            ldsm4(ab + K1_ALO + 16 * ROWB, al[1][0], al[1][1], al[1][2], al[1][3]);
#pragma unroll
            for (int gp = 0; gp < 4; gp++) {
                const uint32_t bb = sb + (uint32_t)(bSec +
                    (16 * gp + laneRow) * ROWB + laneK + 32 * s);
                uint32_t b[4];
                ldsm4(bb, b[0], b[1], b[2], b[3]);
#pragma unroll
                for (int f = 0; f < 2; f++)
#pragma unroll
                    for (int h = 0; h < 2; h++) {
                        float* cc = acc[f][2 * gp + h];
                        hmma(cc, ah[f], b[h], b[2 + h]);
                        hmma(cc, al[f], b[h], b[2 + h]);
                    }
            }
        }
        if (c + 1 < NC1)
            K1_STAGE(sm + (size_t)((c + 1) & 1) * STAGE1, (c + 1) * 32);
    }
#undef K1_STAGE

    // ---- epilogue: up warps park 32x64 tiles in smem; gate warps combine ----
    __syncthreads();
    float* upbuf = reinterpret_cast<float*>(sm);   // 4 x (32 x 68) floats
    if (wid >= 4) {
        float* base = upbuf + (wid - 4) * 2176;
#pragma unroll
        for (int f = 0; f < 2; f++)
#pragma unroll
            for (int n = 0; n < 8; n++) {
                int row = 16 * f + (lane >> 2);
                int col = 8 * n + (lane & 3) * 2;
                float* b0 = base + row * 68 + col;
                b0[0] = acc[f][n][0]; b0[1] = acc[f][n][1];
                float* b1 = b0 + 8 * 68;
                b1[0] = acc[f][n][2]; b1[1] = acc[f][n][3];
            }
    }
    __syncthreads();
    if (wid < 4) {
        const float* base = upbuf + wid * 2176;
#pragma unroll
        for (int f = 0; f < 2; f++)
#pragma unroll
            for (int n = 0; n < 8; n++) {
                int row = 16 * f + (lane >> 2);
                int col = 8 * n + (lane & 3) * 2;
                const float* b0 = base + row * 68 + col;
                const float* b1 = b0 + 8 * 68;
                float* o0 = g_h + (size_t)(m0 + R + row) * IDIM + n0 + col;
                float* o1 = o0 + (size_t)8 * IDIM;
                *reinterpret_cast<float2*>(o0) =
                    make_float2(silu(acc[f][n][0]) * b0[0],
                                silu(acc[f][n][1]) * b0[1]);
                *reinterpret_cast<float2*>(o1) =
                    make_float2(silu(acc[f][n][2]) * b1[0],
                                silu(acc[f][n][3]) * b1[1]);
            }
    }
}

// ---------------------------------------------------------------------------
// Kernel 2: down projection. CTA 128m x 128n, 8 warps 4m x 2n, 2 CTAs/SM.
// fp16 2-term: A (g_h) split-2, B (Wd) single fp16.
// ---------------------------------------------------------------------------
__global__ __launch_bounds__(256, 2)
void k2_down(const float* __restrict__ Wd)
{
    extern __shared__ __align__(128) char sm[];
    const uint32_t smb = smem_u32(sm);
    const int tid  = threadIdx.x;
    const int wid  = tid >> 5;
    const int lane = tid & 31;
    const int m0 = blockIdx.x * 128;
    const int n0 = blockIdx.y * 128;

    const int rbase = tid >> 3;
    const int c4    = (tid & 7) * 4;
    const float *pA[4], *pB[4];
    int sts[4];
#pragma unroll
    for (int j = 0; j < 4; j++) {
        int row = rbase + 32 * j;
        pA[j] = g_h + (size_t)(m0 + row) * IDIM + c4;
        pB[j] = Wd  + (size_t)(n0 + row) * IDIM + c4;
        sts[j] = row * ROWB + (tid & 7) * 8;
    }

    const int laneRow = ((lane >> 3) & 1) * 8 + (lane & 7);
    const int laneK   = (lane >> 4) * 16;
    const int R       = 32 * (wid & 3);
    const int Cw      = 64 * (wid >> 2);

    float acc[2][8][4];
#pragma unroll
    for (int f = 0; f < 2; f++)
#pragma unroll
        for (int n = 0; n < 8; n++)
#pragma unroll
            for (int q = 0; q < 4; q++) acc[f][n][q] = 0.f;

#define K2_STAGE(DST, K0) do {                                                 \
    char* st = (DST);                                                          \
    float4 a0 = *reinterpret_cast<const float4*>(pA[0] + (K0));                \
    float4 a1 = *reinterpret_cast<const float4*>(pA[1] + (K0));                \
    float4 a2 = *reinterpret_cast<const float4*>(pA[2] + (K0));                \
    float4 a3 = *reinterpret_cast<const float4*>(pA[3] + (K0));                \
    float4 b0 = *reinterpret_cast<const float4*>(pB[0] + (K0));                \
    float4 b1 = *reinterpret_cast<const float4*>(pB[1] + (K0));                \
    float4 b2 = *reinterpret_cast<const float4*>(pB[2] + (K0));                \
    float4 b3 = *reinterpret_cast<const float4*>(pB[3] + (K0));                \
    split_store_h(st + sts[0], st + K2_ALO + sts[0], a0);                      \
    split_store_h(st + sts[1], st + K2_ALO + sts[1], a1);                      \
    split_store_h(st + sts[2], st + K2_ALO + sts[2], a2);                      \
    split_store_h(st + sts[3], st + K2_ALO + sts[3], a3);                      \
    *reinterpret_cast<uint2*>(st + K2_B + sts[0]) = cvt4h(b0);                 \
    *reinterpret_cast<uint2*>(st + K2_B + sts[1]) = cvt4h(b1);                 \
    *reinterpret_cast<uint2*>(st + K2_B + sts[2]) = cvt4h(b2);                 \
    *reinterpret_cast<uint2*>(st + K2_B + sts[3]) = cvt4h(b3);                 \
} while (0)

    K2_STAGE(sm, 0);

#pragma unroll 1
    for (int c = 0; c < NC2; c++) {
        __syncthreads();
        const uint32_t sb = smb + (uint32_t)(c & 1) * STAGE2;
#pragma unroll
        for (int s = 0; s < 2; s++) {
            const uint32_t ab = sb + (uint32_t)((R + laneRow) * ROWB + laneK + 32 * s);
            uint32_t ah[2][4], al[2][4];
            ldsm4(ab,                      ah[0][0], ah[0][1], ah[0][2], ah[0][3]);
            ldsm4(ab + 16 * ROWB,          ah[1][0], ah[1][1], ah[1][2], ah[1][3]);
            ldsm4(ab + K2_ALO,             al[0][0], al[0][1], al[0][2], al[0][3]);
            ldsm4(ab + K2_ALO + 16 * ROWB, al[1][0], al[1][1], al[1][2], al[1][3]);
#pragma unroll
            for (int gp = 0; gp < 4; gp++) {
                const uint32_t bb = sb + (uint32_t)(K2_B +
                    (Cw + 16 * gp + laneRow) * ROWB + laneK + 32 * s);
                uint32_t b[4];
                ldsm4(bb, b[0], b[1], b[2], b[3]);
#pragma unroll
                for (int f = 0; f < 2; f++)
#pragma unroll
                    for (int h = 0; h < 2; h++) {
                        float* cc = acc[f][2 * gp + h];
                        hmma(cc, ah[f], b[h], b[2 + h]);
                        hmma(cc, al[f], b[h], b[2 + h]);
                    }
            }
        }
        if (c + 1 < NC2)
            K2_STAGE(sm + (size_t)((c + 1) & 1) * STAGE2, (c + 1) * 32);
    }
#undef K2_STAGE

    // epilogue: direct fp32 stores
#pragma unroll
    for (int f = 0; f < 2; f++)
#pragma unroll
        for (int n = 0; n < 8; n++) {
            int row = m0 + R + 16 * f + (lane >> 2);
            int col = n0 + Cw + 8 * n + (lane & 3) * 2;
            float* o0 = g_down + (size_t)row * HDIM + col;
            float* o1 = o0 + (size_t)8 * HDIM;
            *reinterpret_cast<float2*>(o0) = make_float2(acc[f][n][0], acc[f][n][1]);
            *reinterpret_cast<float2*>(o1) = make_float2(acc[f][n][2], acc[f][n][3]);
        }
}

// ---------------------------------------------------------------------------
// Kernel 3: scatter
// ---------------------------------------------------------------------------
__global__ __launch_bounds__(256)
void scatter_kernel(const int* __restrict__ scatter_indices,
                    float* __restrict__ out)
{
    const int t = blockIdx.x;
    const int c = scatter_indices[t];
    const float4* src = reinterpret_cast<const float4*>(g_down + (size_t)c * HDIM);
    float4*       dst = reinterpret_cast<float4*>(out + (size_t)t * HDIM);
#pragma unroll
    for (int j = threadIdx.x; j < HDIM / 4; j += 256)
        dst[j] = src[j];
}

// ---------------------------------------------------------------------------
extern "C" void kernel_launch(void* const* d_in, const int* in_sizes, int n_in,
                              void* d_out, int out_size)
{
    const float* x  = (const float*)d_in[0];
    const float* Wg = (const float*)d_in[1];
    const float* Wu = (const float*)d_in[2];
    const float* Wd = (const float*)d_in[3];
    const int*   fg = (const int*)d_in[4];
    const int*   sc = (const int*)d_in[5];
    float*       out = (float*)d_out;

    cudaFuncSetAttribute(k1_gateup, cudaFuncAttributeMaxDynamicSharedMemorySize, SMEM1);
    cudaFuncSetAttribute(k2_down,   cudaFuncAttributeMaxDynamicSharedMemorySize, SMEM2);

    dim3 g1(CDIM / 128, IDIM / 64);    // (64 m fastest, 128 n)
    k1_gateup<<<g1, 256, SMEM1>>>(x, Wg, Wu, fg);

    dim3 g2(CDIM / 128, HDIM / 128);   // (64 m fastest, 16 n)
    k2_down<<<g2, 256, SMEM2>>>(Wd);

    scatter_kernel<<<NTOK, 256>>>(sc, out);
}

// round 14
// speedup vs baseline: 1.9714x; 1.3457x over previous
#include <cuda_runtime.h>
#include <cuda_fp16.h>
#include <math.h>
#include <stdint.h>

#define NTOK 16384
#define CDIM 8192
#define HDIM 2048
#define IDIM 8192

// Scratch (allocation-free rule: __device__ globals)
__device__ __align__(256) float g_h[(size_t)CDIM * IDIM];      // silu(g)*u
__device__ __align__(256) float g_down[(size_t)CDIM * HDIM];

// ---------------------------------------------------------------------------
// helpers (plain sm_80-era PTX only)
// ---------------------------------------------------------------------------
__device__ __forceinline__ uint32_t smem_u32(const void* p) {
    return (uint32_t)__cvta_generic_to_shared(p);
}
__device__ __forceinline__ void ldsm4(uint32_t a, uint32_t& r0, uint32_t& r1,
                                      uint32_t& r2, uint32_t& r3) {
    asm volatile("ldmatrix.sync.aligned.m8n8.x4.shared.b16 {%0,%1,%2,%3}, [%4];"
                 : "=r"(r0), "=r"(r1), "=r"(r2), "=r"(r3) : "r"(a));
}
// fp16 x fp16 -> fp32 accum MMA
__device__ __forceinline__ void hmma(float* c, const uint32_t* a,
                                     uint32_t b0, uint32_t b1) {
    asm volatile(
        "mma.sync.aligned.m16n8k16.row.col.f32.f16.f16.f32 "
        "{%0,%1,%2,%3},{%4,%5,%6,%7},{%8,%9},{%0,%1,%2,%3};"
        : "+f"(c[0]), "+f"(c[1]), "+f"(c[2]), "+f"(c[3])
        : "r"(a[0]), "r"(a[1]), "r"(a[2]), "r"(a[3]), "r"(b0), "r"(b1));
}
// fp32x8 -> fp16x8 (16B)
__device__ __forceinline__ uint4 cvt8h(float4 v0, float4 v1) {
    __half2 a = __floats2half2_rn(v0.x, v0.y);
    __half2 b = __floats2half2_rn(v0.z, v0.w);
    __half2 c = __floats2half2_rn(v1.x, v1.y);
    __half2 d = __floats2half2_rn(v1.z, v1.w);
    return make_uint4(*reinterpret_cast<uint32_t*>(&a),
                      *reinterpret_cast<uint32_t*>(&b),
                      *reinterpret_cast<uint32_t*>(&c),
                      *reinterpret_cast<uint32_t*>(&d));
}
// fp32x4 -> fp16x4 (8B)
__device__ __forceinline__ uint2 cvt4h(float4 v) {
    __half2 a = __floats2half2_rn(v.x, v.y);
    __half2 b = __floats2half2_rn(v.z, v.w);
    return make_uint2(*reinterpret_cast<uint32_t*>(&a),
                      *reinterpret_cast<uint32_t*>(&b));
}
__device__ __forceinline__ float silu(float g) { return g / (1.f + __expf(-g)); }

// smem rows: 32 fp16 padded to 40 (80B = 5x16B) — conflict-free ldmatrix
#define ROWB 80
// k1 planes: A(128r) | G(64r) | U(64r)
#define K1_G     10240
#define K1_U     15360
#define STAGE1   20480
#define SMEM1    (2 * STAGE1)   // 40 KB -> 2 CTAs/SM
// k2 planes: A(128r) | B(128r)
#define K2_B     10240
#define STAGE2   20480
#define SMEM2    (2 * STAGE2)   // 40 KB -> 2 CTAs/SM

#define NC1 (HDIM / 32)   // 64 chunks
#define NC2 (IDIM / 32)   // 256 chunks

// ---------------------------------------------------------------------------
// Kernel 1: gather + dual GEMM (gate,up) + SiLU. CTA 128m x 64n, 2 CTAs/SM.
// Warps 0-3 gate (32m x 64n each), warps 4-7 up. Pure fp16 MMA (1/k16).
// ---------------------------------------------------------------------------
__global__ __launch_bounds__(256, 2)
void k1_gateup(const float* __restrict__ x,
               const float* __restrict__ Wg,
               const float* __restrict__ Wu,
               const int* __restrict__ fg)
{
    extern __shared__ __align__(128) char sm[];
    const uint32_t smb = smem_u32(sm);
    const int tid  = threadIdx.x;
    const int wid  = tid >> 5;
    const int lane = tid & 31;
    const int m0 = blockIdx.x * 128;   // m fastest -> B tiles L2-resident
    const int n0 = blockIdx.y * 64;

    // A staging: 8 threads/row, one float4 each, 4 rows/thread -> fp16x4
    const int rbase = tid >> 3;
    const int c4    = (tid & 7) * 4;
    const float* pA[4];
    int stsA[4];
#pragma unroll
    for (int j = 0; j < 4; j++) {
        int row = rbase + 32 * j;
        pA[j] = x + (size_t)__ldg(fg + m0 + row) * HDIM + c4;
        stsA[j] = row * ROWB + (tid & 7) * 8;
    }
    // B staging: 64 rows, 4 threads/row, 8 floats -> 8 fp16 (16B) per matrix
    const int brow = tid >> 2;
    const float* pG = Wg + (size_t)(n0 + brow) * HDIM + (tid & 3) * 8;
    const float* pU = Wu + (size_t)(n0 + brow) * HDIM + (tid & 3) * 8;
    const int stsB = brow * ROWB + (tid & 3) * 16;

    // ldmatrix lane geometry
    const int laneRow = ((lane >> 3) & 1) * 8 + (lane & 7);
    const int laneK   = (lane >> 4) * 16;
    const int R       = 32 * (wid & 3);
    const int bSec    = (wid >= 4) ? K1_U : K1_G;

    float acc[2][8][4];
#pragma unroll
    for (int f = 0; f < 2; f++)
#pragma unroll
        for (int n = 0; n < 8; n++)
#pragma unroll
            for (int q = 0; q < 4; q++) acc[f][n][q] = 0.f;

#define K1_STAGE(DST, K0) do {                                                 \
    char* st = (DST);                                                          \
    float4 a0 = *reinterpret_cast<const float4*>(pA[0] + (K0));                \
    float4 a1 = *reinterpret_cast<const float4*>(pA[1] + (K0));                \
    float4 a2 = *reinterpret_cast<const float4*>(pA[2] + (K0));                \
    float4 a3 = *reinterpret_cast<const float4*>(pA[3] + (K0));                \
    float4 gg0 = *reinterpret_cast<const float4*>(pG + (K0));                  \
    float4 gg1 = *reinterpret_cast<const float4*>(pG + (K0) + 4);              \
    float4 uu0 = *reinterpret_cast<const float4*>(pU + (K0));                  \
    float4 uu1 = *reinterpret_cast<const float4*>(pU + (K0) + 4);              \
    *reinterpret_cast<uint2*>(st + stsA[0]) = cvt4h(a0);                       \
    *reinterpret_cast<uint2*>(st + stsA[1]) = cvt4h(a1);                       \
    *reinterpret_cast<uint2*>(st + stsA[2]) = cvt4h(a2);                       \
    *reinterpret_cast<uint2*>(st + stsA[3]) = cvt4h(a3);                       \
    *reinterpret_cast<uint4*>(st + K1_G + stsB) = cvt8h(gg0, gg1);             \
    *reinterpret_cast<uint4*>(st + K1_U + stsB) = cvt8h(uu0, uu1);             \
} while (0)

    K1_STAGE(sm, 0);

#pragma unroll 1
    for (int c = 0; c < NC1; c++) {
        __syncthreads();
        const uint32_t sb = smb + (uint32_t)(c & 1) * STAGE1;
#pragma unroll
        for (int s = 0; s < 2; s++) {
            const uint32_t ab = sb + (uint32_t)((R + laneRow) * ROWB + laneK + 32 * s);
            uint32_t ah[2][4];
            ldsm4(ab,             ah[0][0], ah[0][1], ah[0][2], ah[0][3]);
            ldsm4(ab + 16 * ROWB, ah[1][0], ah[1][1], ah[1][2], ah[1][3]);
#pragma unroll
            for (int gp = 0; gp < 4; gp++) {
                const uint32_t bb = sb + (uint32_t)(bSec +
                    (16 * gp + laneRow) * ROWB + laneK + 32 * s);
                uint32_t b[4];
                ldsm4(bb, b[0], b[1], b[2], b[3]);
#pragma unroll
                for (int f = 0; f < 2; f++)
#pragma unroll
                    for (int h = 0; h < 2; h++)
                        hmma(acc[f][2 * gp + h], ah[f], b[h], b[2 + h]);
            }
        }
        if (c + 1 < NC1)
            K1_STAGE(sm + (size_t)((c + 1) & 1) * STAGE1, (c + 1) * 32);
    }
#undef K1_STAGE

    // ---- epilogue: up warps park 32x64 tiles in smem; gate warps combine ----
    __syncthreads();
    float* upbuf = reinterpret_cast<float*>(sm);   // 4 x (32 x 68) floats
    if (wid >= 4) {
        float* base = upbuf + (wid - 4) * 2176;
#pragma unroll
        for (int f = 0; f < 2; f++)
#pragma unroll
            for (int n = 0; n < 8; n++) {
                int row = 16 * f + (lane >> 2);
                int col = 8 * n + (lane & 3) * 2;
                float* b0 = base + row * 68 + col;
                b0[0] = acc[f][n][0]; b0[1] = acc[f][n][1];
                float* b1 = b0 + 8 * 68;
                b1[0] = acc[f][n][2]; b1[1] = acc[f][n][3];
            }
    }
    __syncthreads();
    if (wid < 4) {
        const float* base = upbuf + wid * 2176;
#pragma unroll
        for (int f = 0; f < 2; f++)
#pragma unroll
            for (int n = 0; n < 8; n++) {
                int row = 16 * f + (lane >> 2);
                int col = 8 * n + (lane & 3) * 2;
                const float* b0 = base + row * 68 + col;
                const float* b1 = b0 + 8 * 68;
                float* o0 = g_h + (size_t)(m0 + R + row) * IDIM + n0 + col;
                float* o1 = o0 + (size_t)8 * IDIM;
                *reinterpret_cast<float2*>(o0) =
                    make_float2(silu(acc[f][n][0]) * b0[0],
                                silu(acc[f][n][1]) * b0[1]);
                *reinterpret_cast<float2*>(o1) =
                    make_float2(silu(acc[f][n][2]) * b1[0],
                                silu(acc[f][n][3]) * b1[1]);
            }
    }
}

// ---------------------------------------------------------------------------
// Kernel 2: down projection. CTA 128m x 128n, 8 warps 4m x 2n, 2 CTAs/SM.
// Pure fp16 MMA.
// ---------------------------------------------------------------------------
__global__ __launch_bounds__(256, 2)
void k2_down(const float* __restrict__ Wd)
{
    extern __shared__ __align__(128) char sm[];
    const uint32_t smb = smem_u32(sm);
    const int tid  = threadIdx.x;
    const int wid  = tid >> 5;
    const int lane = tid & 31;
    const int m0 = blockIdx.x * 128;
    const int n0 = blockIdx.y * 128;

    const int rbase = tid >> 3;
    const int c4    = (tid & 7) * 4;
    const float *pA[4], *pB[4];
    int sts[4];
#pragma unroll
    for (int j = 0; j < 4; j++) {
        int row = rbase + 32 * j;
        pA[j] = g_h + (size_t)(m0 + row) * IDIM + c4;
        pB[j] = Wd  + (size_t)(n0 + row) * IDIM + c4;
        sts[j] = row * ROWB + (tid & 7) * 8;
    }

    const int laneRow = ((lane >> 3) & 1) * 8 + (lane & 7);
    const int laneK   = (lane >> 4) * 16;
    const int R       = 32 * (wid & 3);
    const int Cw      = 64 * (wid >> 2);

    float acc[2][8][4];
#pragma unroll
    for (int f = 0; f < 2; f++)
#pragma unroll
        for (int n = 0; n < 8; n++)
#pragma unroll
            for (int q = 0; q < 4; q++) acc[f][n][q] = 0.f;

#define K2_STAGE(DST, K0) do {                                                 \
    char* st = (DST);                                                          \
    float4 a0 = *reinterpret_cast<const float4*>(pA[0] + (K0));                \
    float4 a1 = *reinterpret_cast<const float4*>(pA[1] + (K0));                \
    float4 a2 = *reinterpret_cast<const float4*>(pA[2] + (K0));                \
    float4 a3 = *reinterpret_cast<const float4*>(pA[3] + (K0));                \
    float4 b0 = *reinterpret_cast<const float4*>(pB[0] + (K0));                \
    float4 b1 = *reinterpret_cast<const float4*>(pB[1] + (K0));                \
    float4 b2 = *reinterpret_cast<const float4*>(pB[2] + (K0));                \
    float4 b3 = *reinterpret_cast<const float4*>(pB[3] + (K0));                \
    *reinterpret_cast<uint2*>(st + sts[0]) = cvt4h(a0);                        \
    *reinterpret_cast<uint2*>(st + sts[1]) = cvt4h(a1);                        \
    *reinterpret_cast<uint2*>(st + sts[2]) = cvt4h(a2);                        \
    *reinterpret_cast<uint2*>(st + sts[3]) = cvt4h(a3);                        \
    *reinterpret_cast<uint2*>(st + K2_B + sts[0]) = cvt4h(b0);                 \
    *reinterpret_cast<uint2*>(st + K2_B + sts[1]) = cvt4h(b1);                 \
    *reinterpret_cast<uint2*>(st + K2_B + sts[2]) = cvt4h(b2);                 \
    *reinterpret_cast<uint2*>(st + K2_B + sts[3]) = cvt4h(b3);                 \
} while (0)

    K2_STAGE(sm, 0);

#pragma unroll 1
    for (int c = 0; c < NC2; c++) {
        __syncthreads();
        const uint32_t sb = smb + (uint32_t)(c & 1) * STAGE2;
#pragma unroll
        for (int s = 0; s < 2; s++) {
            const uint32_t ab = sb + (uint32_t)((R + laneRow) * ROWB + laneK + 32 * s);
            uint32_t ah[2][4];
            ldsm4(ab,             ah[0][0], ah[0][1], ah[0][2], ah[0][3]);
            ldsm4(ab + 16 * ROWB, ah[1][0], ah[1][1], ah[1][2], ah[1][3]);
#pragma unroll
            for (int gp = 0; gp < 4; gp++) {
                const uint32_t bb = sb + (uint32_t)(K2_B +
                    (Cw + 16 * gp + laneRow) * ROWB + laneK + 32 * s);
                uint32_t b[4];
                ldsm4(bb, b[0], b[1], b[2], b[3]);
#pragma unroll
                for (int f = 0; f < 2; f++)
#pragma unroll
                    for (int h = 0; h < 2; h++)
                        hmma(acc[f][2 * gp + h], ah[f], b[h], b[2 + h]);
            }
        }
        if (c + 1 < NC2)
            K2_STAGE(sm + (size_t)((c + 1) & 1) * STAGE2, (c + 1) * 32);
    }
#undef K2_STAGE

    // epilogue: direct fp32 stores
#pragma unroll
    for (int f = 0; f < 2; f++)
#pragma unroll
        for (int n = 0; n < 8; n++) {
            int row = m0 + R + 16 * f + (lane >> 2);
            int col = n0 + Cw + 8 * n + (lane & 3) * 2;
            float* o0 = g_down + (size_t)row * HDIM + col;
            float* o1 = o0 + (size_t)8 * HDIM;
            *reinterpret_cast<float2*>(o0) = make_float2(acc[f][n][0], acc[f][n][1]);
            *reinterpret_cast<float2*>(o1) = make_float2(acc[f][n][2], acc[f][n][3]);
        }
}

// ---------------------------------------------------------------------------
// Kernel 3: scatter
// ---------------------------------------------------------------------------
__global__ __launch_bounds__(256)
void scatter_kernel(const int* __restrict__ scatter_indices,
                    float* __restrict__ out)
{
    const int t = blockIdx.x;
    const int c = scatter_indices[t];
    const float4* src = reinterpret_cast<const float4*>(g_down + (size_t)c * HDIM);
    float4*       dst = reinterpret_cast<float4*>(out + (size_t)t * HDIM);
#pragma unroll
    for (int j = threadIdx.x; j < HDIM / 4; j += 256)
        dst[j] = src[j];
}

// ---------------------------------------------------------------------------
extern "C" void kernel_launch(void* const* d_in, const int* in_sizes, int n_in,
                              void* d_out, int out_size)
{
    const float* x  = (const float*)d_in[0];
    const float* Wg = (const float*)d_in[1];
    const float* Wu = (const float*)d_in[2];
    const float* Wd = (const float*)d_in[3];
    const int*   fg = (const int*)d_in[4];
    const int*   sc = (const int*)d_in[5];
    float*       out = (float*)d_out;

    cudaFuncSetAttribute(k1_gateup, cudaFuncAttributeMaxDynamicSharedMemorySize, SMEM1);
    cudaFuncSetAttribute(k2_down,   cudaFuncAttributeMaxDynamicSharedMemorySize, SMEM2);

    dim3 g1(CDIM / 128, IDIM / 64);    // (64 m fastest, 128 n)
    k1_gateup<<<g1, 256, SMEM1>>>(x, Wg, Wu, fg);

    dim3 g2(CDIM / 128, HDIM / 128);   // (64 m fastest, 16 n)
    k2_down<<<g2, 256, SMEM2>>>(Wd);

    scatter_kernel<<<NTOK, 256>>>(sc, out);
}